// round 10
// baseline (speedup 1.0000x reference)
#include <cuda_runtime.h>
#include <cuda_bf16.h>
#include <math.h>
#include <float.h>
#include <stdint.h>

// Problem constants
#define T_TOK 8192
#define D_DIM 7168
#define E_EXP 256
#define N_GROUPS 8
#define TOPK_GROUPS 4
#define TOP_K 8

// Margin thresholds (score scale); MMA score error ~1e-7 << EPS
#define EPS_E 1e-4f
#define EPS_G 2e-4f

// GEMM tiling (mma.sync m16n8k16 bf16, 2-way split, 3 terms)
#define BM 128
#define BN 128
#define KC 64
#define NCHUNK (D_DIM / KC)        // 112
#define FLUSH 4

#define STRD 72
#define ARR_BYTES (128 * STRD * 2)          // 18432
#define OFF_XH 0
#define OFF_XM (1 * ARR_BYTES)
#define OFF_WH (2 * ARR_BYTES)
#define OFF_WM (3 * ARR_BYTES)
#define STAGE_BYTES (4 * ARR_BYTES)         // 73728
#define SMEM_BYTES (2 * STAGE_BYTES)        // 147456

// Scratch (no allocs allowed)
__device__ float         g_scores[(size_t)T_TOK * E_EXP];
__device__ __nv_bfloat16 g_w_h[(size_t)E_EXP * D_DIM];
__device__ __nv_bfloat16 g_w_m[(size_t)E_EXP * D_DIM];
__device__ int           g_nflag;
__device__ int           g_flaglist[T_TOK];

// ---------------------------------------------------------------------------
__device__ __forceinline__ uint32_t s2u(const void* p) {
    uint32_t a;
    asm("{ .reg .u64 t; cvta.to.shared.u64 t, %1; cvt.u32.u64 %0, t; }" : "=r"(a) : "l"(p));
    return a;
}

__device__ __forceinline__ void mma16816(float d[4], const uint32_t a[4], const uint32_t b[2]) {
    asm volatile(
        "mma.sync.aligned.m16n8k16.row.col.f32.bf16.bf16.f32 "
        "{%0,%1,%2,%3}, {%4,%5,%6,%7}, {%8,%9}, {%0,%1,%2,%3};"
        : "+f"(d[0]), "+f"(d[1]), "+f"(d[2]), "+f"(d[3])
        : "r"(a[0]), "r"(a[1]), "r"(a[2]), "r"(a[3]), "r"(b[0]), "r"(b[1]));
}

#define CP_ASYNC16(smem_u32, gptr) \
    asm volatile("cp.async.cg.shared.global [%0], [%1], 16;" \
        :: "r"(smem_u32), "l"(gptr) : "memory")
#define CP_COMMIT() asm volatile("cp.async.commit_group;" ::: "memory")
#define CP_WAIT0()  asm volatile("cp.async.wait_group 0;" ::: "memory")

__device__ __forceinline__ uint32_t pack_bf2(float a, float b) {
    __nv_bfloat162 h = __floats2bfloat162_rn(a, b);
    return *reinterpret_cast<uint32_t*>(&h);
}

__device__ __forceinline__ void split2(float x, float& h, float& m) {
    __nv_bfloat16 hb = __float2bfloat16(x);
    h = __bfloat162float(hb);
    m = x - h;
}

// ---------------------------------------------------------------------------
// Kernel Z: reset flag counter
// ---------------------------------------------------------------------------
__global__ void zero_flags_kernel() {
    if (threadIdx.x == 0) g_nflag = 0;
}

// ---------------------------------------------------------------------------
// Kernel 0: transpose + 2-way bf16 split W[D,E] -> g_w_{h,m}[E][D]
// ---------------------------------------------------------------------------
__global__ __launch_bounds__(256)
void prep_w_kernel(const float* __restrict__ W)
{
    __shared__ float tile[32][33];
    const int eb = blockIdx.x * 32;
    const int kb = blockIdx.y * 32;
    const int x = threadIdx.x, y = threadIdx.y;
#pragma unroll
    for (int j = 0; j < 32; j += 8)
        tile[y + j][x] = W[(size_t)(kb + y + j) * E_EXP + eb + x];
    __syncthreads();
#pragma unroll
    for (int j = 0; j < 32; j += 8) {
        float w = tile[x][y + j];
        float h, m;
        split2(w, h, m);
        size_t o = (size_t)(eb + y + j) * D_DIM + kb + x;
        g_w_h[o] = __float2bfloat16(h);
        g_w_m[o] = __float2bfloat16(m);
    }
}

// ---------------------------------------------------------------------------
// GEMM stage helpers (validated R6/R9 layout)
// ---------------------------------------------------------------------------
__device__ __forceinline__ void issue_w_cpasync(uint32_t stage_u32, int n_base, int k0, int tid)
{
#pragma unroll
    for (int j = 0; j < 4; j++) {
        int c = tid + j * 256;
        int row = c >> 3, seg = c & 7;
        size_t g = (size_t)(n_base + row) * D_DIM + k0 + seg * 8;
        uint32_t so = (uint32_t)(row * STRD + seg * 8) * 2;
        CP_ASYNC16(stage_u32 + OFF_WH + so, (const void*)(g_w_h + g));
        CP_ASYNC16(stage_u32 + OFF_WM + so, (const void*)(g_w_m + g));
    }
    CP_COMMIT();
}

__device__ __forceinline__ void issue_x_loads(const float* __restrict__ X,
                                              int m_base, int k0, int tid, float4 xa[8])
{
#pragma unroll
    for (int j = 0; j < 8; j++) {
        int f = tid + j * 256;
        int row = f >> 4, c4 = (f & 15) << 2;
        xa[j] = *(const float4*)(X + (size_t)(m_base + row) * D_DIM + k0 + c4);
    }
}

__device__ __forceinline__ void store_x(char* stage, int tid, const float4 xa[8])
{
#pragma unroll
    for (int j = 0; j < 8; j++) {
        int f = tid + j * 256;
        int row = f >> 4, c4 = (f & 15) << 2;
        float xs[4] = {xa[j].x, xa[j].y, xa[j].z, xa[j].w};
        float h[4], m[4];
#pragma unroll
        for (int e = 0; e < 4; e++) split2(xs[e], h[e], m[e]);
        uint32_t so = (uint32_t)(row * STRD + c4) * 2;
        *(uint2*)(stage + OFF_XH + so) = make_uint2(pack_bf2(h[0], h[1]), pack_bf2(h[2], h[3]));
        *(uint2*)(stage + OFF_XM + so) = make_uint2(pack_bf2(m[0], m[1]), pack_bf2(m[2], m[3]));
    }
}

__device__ __forceinline__ void compute_stage(const char* stage, int wm, int wn,
                                              int g, int q, float acc_c[4][4][4])
{
#pragma unroll
    for (int kk = 0; kk < 4; kk++) {
        uint32_t wh[4][2], wv[4][2];
#pragma unroll
        for (int nt = 0; nt < 4; nt++) {
            uint32_t off = ((uint32_t)(wn * 32 + nt * 8 + g) * STRD + kk * 16 + q * 2) * 2;
            wh[nt][0] = *(const uint32_t*)(stage + OFF_WH + off);
            wh[nt][1] = *(const uint32_t*)(stage + OFF_WH + off + 16);
            wv[nt][0] = *(const uint32_t*)(stage + OFF_WM + off);
            wv[nt][1] = *(const uint32_t*)(stage + OFF_WM + off + 16);
        }
#pragma unroll
        for (int mt = 0; mt < 4; mt++) {
            uint32_t off = ((uint32_t)(wm * 64 + mt * 16 + g) * STRD + kk * 16 + q * 2) * 2;
            const uint32_t r8 = 8 * STRD * 2;
            uint32_t xh[4], xm[4];
            xh[0] = *(const uint32_t*)(stage + OFF_XH + off);
            xh[1] = *(const uint32_t*)(stage + OFF_XH + off + r8);
            xh[2] = *(const uint32_t*)(stage + OFF_XH + off + 16);
            xh[3] = *(const uint32_t*)(stage + OFF_XH + off + r8 + 16);
            xm[0] = *(const uint32_t*)(stage + OFF_XM + off);
            xm[1] = *(const uint32_t*)(stage + OFF_XM + off + r8);
            xm[2] = *(const uint32_t*)(stage + OFF_XM + off + 16);
            xm[3] = *(const uint32_t*)(stage + OFF_XM + off + r8 + 16);
#pragma unroll
            for (int nt = 0; nt < 4; nt++) {
                mma16816(acc_c[mt][nt], xh, wh[nt]);
                mma16816(acc_c[mt][nt], xh, wv[nt]);
                mma16816(acc_c[mt][nt], xm, wh[nt]);
            }
        }
    }
}

// ---------------------------------------------------------------------------
// Kernel 1: bf16 2-way-split warp-MMA GEMM, chunked accumulation, sigmoid
// ---------------------------------------------------------------------------
__global__ __launch_bounds__(256, 1)
void gemm_mma_kernel(const float* __restrict__ X)
{
    extern __shared__ __align__(16) char sm[];
    const uint32_t sm_u32 = s2u(sm);
    const int tid  = threadIdx.x;
    const int lane = tid & 31;
    const int wid  = tid >> 5;
    const int wm = wid & 1;
    const int wn = wid >> 1;
    const int g = lane >> 2;
    const int q = lane & 3;
    const int n_base = blockIdx.x * BN;
    const int m_base = blockIdx.y * BM;

    float acc_t[4][4][4], acc_c[4][4][4];
#pragma unroll
    for (int a = 0; a < 4; a++)
#pragma unroll
        for (int b = 0; b < 4; b++)
#pragma unroll
            for (int c = 0; c < 4; c++) { acc_t[a][b][c] = 0.0f; acc_c[a][b][c] = 0.0f; }

    float4 xa[8];

    issue_w_cpasync(sm_u32, n_base, 0, tid);
    issue_x_loads(X, m_base, 0, tid, xa);
    store_x(sm, tid, xa);
    CP_WAIT0();
    __syncthreads();

    for (int ic = 0; ic < NCHUNK; ic++) {
        char* cur = sm + (size_t)(ic & 1) * STAGE_BYTES;
        char* nxt = sm + (size_t)((ic & 1) ^ 1) * STAGE_BYTES;
        const uint32_t nxt_u32 = sm_u32 + (uint32_t)(((ic & 1) ^ 1) * STAGE_BYTES);
        const bool pf = (ic + 1 < NCHUNK);
        if (pf) {
            issue_w_cpasync(nxt_u32, n_base, (ic + 1) * KC, tid);
            issue_x_loads(X, m_base, (ic + 1) * KC, tid, xa);
        }
        compute_stage(cur, wm, wn, g, q, acc_c);
        if ((ic & (FLUSH - 1)) == (FLUSH - 1)) {
#pragma unroll
            for (int a = 0; a < 4; a++)
#pragma unroll
                for (int b = 0; b < 4; b++)
#pragma unroll
                    for (int c = 0; c < 4; c++) {
                        acc_t[a][b][c] += acc_c[a][b][c];
                        acc_c[a][b][c] = 0.0f;
                    }
        }
        if (pf) store_x(nxt, tid, xa);
        CP_WAIT0();
        __syncthreads();
    }

#pragma unroll
    for (int mt = 0; mt < 4; mt++) {
#pragma unroll
        for (int nt = 0; nt < 4; nt++) {
            int row = m_base + wm * 64 + mt * 16 + g;
            int col = n_base + wn * 32 + nt * 8 + q * 2;
            float s0 = 1.0f / (1.0f + expf(-acc_t[mt][nt][0]));
            float s1 = 1.0f / (1.0f + expf(-acc_t[mt][nt][1]));
            float s2 = 1.0f / (1.0f + expf(-acc_t[mt][nt][2]));
            float s3 = 1.0f / (1.0f + expf(-acc_t[mt][nt][3]));
            *(float2*)(g_scores + (size_t)row * E_EXP + col)       = make_float2(s0, s1);
            *(float2*)(g_scores + (size_t)(row + 8) * E_EXP + col) = make_float2(s2, s3);
        }
    }
}

// ---------------------------------------------------------------------------
// Shared routing body. mode 0: flag borderline tokens. mode 1: force-write.
// Call with full 256-thread block.
// ---------------------------------------------------------------------------
__device__ __forceinline__ void route_one(int t, const float* __restrict__ bias,
                                          float* __restrict__ out, int write_indices,
                                          int mode)
{
    __shared__ float score_sh[E_EXP];
    __shared__ float s_sh[E_EXP];
    __shared__ float gscore[N_GROUPS];
    __shared__ int   gsel[N_GROUPS];
    __shared__ float gmargin_sh;

    const int tid  = threadIdx.x;
    const int lane = tid & 31;
    const int wid  = tid >> 5;

    const float sc = g_scores[(size_t)t * E_EXP + tid];
    const float s  = sc + bias[tid];
    score_sh[tid] = sc;

    // group score: top-2 within warp/group
    float v1 = s; int i1 = lane;
#pragma unroll
    for (int o = 16; o; o >>= 1) {
        float ov = __shfl_xor_sync(0xffffffffu, v1, o);
        int   oi = __shfl_xor_sync(0xffffffffu, i1, o);
        if (ov > v1 || (ov == v1 && oi < i1)) { v1 = ov; i1 = oi; }
    }
    float v2 = (lane == i1) ? -FLT_MAX : s;
#pragma unroll
    for (int o = 16; o; o >>= 1) {
        float ov = __shfl_xor_sync(0xffffffffu, v2, o);
        if (ov > v2) v2 = ov;
    }
    if (lane == 0) gscore[wid] = v1 + v2;
    if (tid < N_GROUPS) gsel[tid] = 0;
    __syncthreads();

    // top-4 groups + margin (4th vs 5th)
    if (tid == 0) {
        float gg[N_GROUPS];
#pragma unroll
        for (int i = 0; i < N_GROUPS; i++) gg[i] = gscore[i];
        float v4 = 0.0f;
#pragma unroll
        for (int r = 0; r < TOPK_GROUPS; r++) {
            int best = 0; float bv = gg[0];
#pragma unroll
            for (int i = 1; i < N_GROUPS; i++)
                if (gg[i] > bv) { bv = gg[i]; best = i; }
            gsel[best] = 1;
            gg[best] = -FLT_MAX;
            v4 = bv;
        }
        float g5 = -FLT_MAX;
#pragma unroll
        for (int i = 0; i < N_GROUPS; i++)
            if (gg[i] > g5) g5 = gg[i];
        gmargin_sh = v4 - g5;
    }
    __syncthreads();

    s_sh[tid] = gsel[wid] ? s : 0.0f;
    __syncthreads();

    if (wid == 0) {
        float vals[8]; int idxs[8];
#pragma unroll
        for (int r = 0; r < 8; r++) {
            idxs[r] = r * 32 + lane;
            vals[r] = s_sh[idxs[r]];
        }
        int top[TOP_K];
        float topv9 = 0.0f, topv8 = 0.0f;
#pragma unroll
        for (int r = 0; r < TOP_K + 1; r++) {      // 9 rounds: 8 picks + 9th value
            float bv = vals[0]; int bi = idxs[0]; int bslot = 0;
#pragma unroll
            for (int qq = 1; qq < 8; qq++)
                if (vals[qq] > bv || (vals[qq] == bv && idxs[qq] < bi)) {
                    bv = vals[qq]; bi = idxs[qq]; bslot = qq;
                }
            float wv2 = bv; int wi = bi;
#pragma unroll
            for (int o = 16; o; o >>= 1) {
                float ov = __shfl_xor_sync(0xffffffffu, wv2, o);
                int   oi = __shfl_xor_sync(0xffffffffu, wi, o);
                if (ov > wv2 || (ov == wv2 && oi < wi)) { wv2 = ov; wi = oi; }
            }
            if (bi == wi) vals[bslot] = -FLT_MAX;
            if (r < TOP_K) { top[r] = wi; if (r == TOP_K - 1) topv8 = wv2; }
            else           topv9 = wv2;
        }

        float w = 0.0f; int myidx = 0;
        if (lane < TOP_K) { myidx = top[lane]; w = score_sh[myidx]; }
        float sum = w;
#pragma unroll
        for (int o = 16; o; o >>= 1) sum += __shfl_xor_sync(0xffffffffu, sum, o);
        float weight = w / (sum + 1e-20f) * 2.5f;

        if (lane < TOP_K) {
            out[(size_t)t * TOP_K + lane] = weight;
            if (write_indices)
                out[(size_t)T_TOK * TOP_K + (size_t)t * TOP_K + lane] = (float)myidx;
        }

        if (mode == 0 && lane == 0) {
            bool safe = (gmargin_sh > EPS_G) && ((topv8 - topv9) > EPS_E);
            if (!safe) {
                int pos = atomicAdd(&g_nflag, 1);
                g_flaglist[pos] = t;
            }
        }
    }
    __syncthreads();
}

// ---------------------------------------------------------------------------
// Kernel 2: router pass 1 (all tokens, flag borderline)
// ---------------------------------------------------------------------------
__global__ __launch_bounds__(256)
void router_kernel(const float* __restrict__ bias, float* __restrict__ out,
                   int write_indices)
{
    route_one(blockIdx.x, bias, out, write_indices, 0);
}

// ---------------------------------------------------------------------------
// Kernel 3: exact rescore of flagged tokens (bit-identical to R2 fp32 path:
// serial-k FMA per (token, expert), then sigmoid). 2 tokens per block.
// ---------------------------------------------------------------------------
#define RS_CHK 1024
__global__ __launch_bounds__(256)
void rescore_kernel(const float* __restrict__ X, const float* __restrict__ W)
{
    __shared__ float xs[2][RS_CHK];
    const int n = g_nflag;
    const int e = threadIdx.x;

    for (int base = blockIdx.x * 2; base < n; base += gridDim.x * 2) {
        const int t0 = g_flaglist[base];
        const bool has1 = (base + 1 < n);
        const int t1 = has1 ? g_flaglist[base + 1] : t0;

        float acc0 = 0.0f, acc1 = 0.0f;
        for (int k0 = 0; k0 < D_DIM; k0 += RS_CHK) {
            // load X chunks for both tokens
            for (int idx = e; idx < 2 * RS_CHK; idx += 256) {
                int row = idx >> 10, k = idx & (RS_CHK - 1);
                int tt = row ? t1 : t0;
                xs[row][k] = X[(size_t)tt * D_DIM + k0 + k];
            }
            __syncthreads();
#pragma unroll 8
            for (int k = 0; k < RS_CHK; k++) {
                float w = W[(size_t)(k0 + k) * E_EXP + e];
                acc0 = fmaf(xs[0][k], w, acc0);
                acc1 = fmaf(xs[1][k], w, acc1);
            }
            __syncthreads();
        }
        g_scores[(size_t)t0 * E_EXP + e] = 1.0f / (1.0f + expf(-acc0));
        if (has1)
            g_scores[(size_t)t1 * E_EXP + e] = 1.0f / (1.0f + expf(-acc1));
    }
}

// ---------------------------------------------------------------------------
// Kernel 4: re-route flagged tokens with exact scores (force write)
// ---------------------------------------------------------------------------
__global__ __launch_bounds__(256)
void router_fix_kernel(const float* __restrict__ bias, float* __restrict__ out,
                       int write_indices)
{
    const int n = g_nflag;
    for (int i = blockIdx.x; i < n; i += gridDim.x)
        route_one(g_flaglist[i], bias, out, write_indices, 1);
}

// ---------------------------------------------------------------------------
extern "C" void kernel_launch(void* const* d_in, const int* in_sizes, int n_in,
                              void* d_out, int out_size)
{
    const float* X    = (const float*)d_in[0];   // [T, D]
    const float* W    = (const float*)d_in[1];   // [D, E]
    const float* bias = (const float*)d_in[2];   // [E]
    float* out = (float*)d_out;

    cudaFuncSetAttribute(gemm_mma_kernel,
                         cudaFuncAttributeMaxDynamicSharedMemorySize, SMEM_BYTES);

    int write_indices = (out_size >= 2 * T_TOK * TOP_K) ? 1 : 0;

    zero_flags_kernel<<<1, 32>>>();
    prep_w_kernel<<<dim3(E_EXP / 32, D_DIM / 32), dim3(32, 8)>>>(W);
    gemm_mma_kernel<<<dim3(E_EXP / BN, T_TOK / BM), 256, SMEM_BYTES>>>(X);
    router_kernel<<<T_TOK, 256>>>(bias, out, write_indices);
    rescore_kernel<<<128, 256>>>(X, W);
    router_fix_kernel<<<256, 256>>>(bias, out, write_indices);
}

// round 11
// speedup vs baseline: 1.0563x; 1.0563x over previous
#include <cuda_runtime.h>
#include <cuda_bf16.h>
#include <math.h>
#include <float.h>
#include <stdint.h>

// Problem constants
#define T_TOK 8192
#define D_DIM 7168
#define E_EXP 256
#define N_GROUPS 8
#define TOPK_GROUPS 4
#define TOP_K 8

// Margin thresholds (score scale); pass-1 MMA score error ~1e-6 << EPS
#define EPS_E 1e-4f
#define EPS_G 2e-4f

// GEMM tiling (mma.sync m16n8k16 bf16, 2-way split, 3 terms)
#define BM 128
#define BN 128
#define KC 64
#define NCHUNK (D_DIM / KC)        // 112

#define STRD 72
#define ARR_BYTES (128 * STRD * 2)          // 18432
#define OFF_XH 0
#define OFF_XM (1 * ARR_BYTES)
#define OFF_WH (2 * ARR_BYTES)
#define OFF_WM (3 * ARR_BYTES)
#define STAGE_BYTES (4 * ARR_BYTES)         // 73728
#define SMEM_BYTES (2 * STAGE_BYTES)        // 147456

// Scratch (no allocs allowed)
__device__ float         g_scores[(size_t)T_TOK * E_EXP];
__device__ __nv_bfloat16 g_w_h[(size_t)E_EXP * D_DIM];
__device__ __nv_bfloat16 g_w_m[(size_t)E_EXP * D_DIM];
__device__ int           g_nflag;
__device__ int           g_flaglist[T_TOK];

// ---------------------------------------------------------------------------
__device__ __forceinline__ uint32_t s2u(const void* p) {
    uint32_t a;
    asm("{ .reg .u64 t; cvta.to.shared.u64 t, %1; cvt.u32.u64 %0, t; }" : "=r"(a) : "l"(p));
    return a;
}

__device__ __forceinline__ void mma16816(float d[4], const uint32_t a[4], const uint32_t b[2]) {
    asm volatile(
        "mma.sync.aligned.m16n8k16.row.col.f32.bf16.bf16.f32 "
        "{%0,%1,%2,%3}, {%4,%5,%6,%7}, {%8,%9}, {%0,%1,%2,%3};"
        : "+f"(d[0]), "+f"(d[1]), "+f"(d[2]), "+f"(d[3])
        : "r"(a[0]), "r"(a[1]), "r"(a[2]), "r"(a[3]), "r"(b[0]), "r"(b[1]));
}

#define CP_ASYNC16(smem_u32, gptr) \
    asm volatile("cp.async.cg.shared.global [%0], [%1], 16;" \
        :: "r"(smem_u32), "l"(gptr) : "memory")
#define CP_COMMIT() asm volatile("cp.async.commit_group;" ::: "memory")
#define CP_WAIT0()  asm volatile("cp.async.wait_group 0;" ::: "memory")

__device__ __forceinline__ uint32_t pack_bf2(float a, float b) {
    __nv_bfloat162 h = __floats2bfloat162_rn(a, b);
    return *reinterpret_cast<uint32_t*>(&h);
}

__device__ __forceinline__ void split2(float x, float& h, float& m) {
    __nv_bfloat16 hb = __float2bfloat16(x);
    h = __bfloat162float(hb);
    m = x - h;
}

// ---------------------------------------------------------------------------
__global__ void zero_flags_kernel() {
    if (threadIdx.x == 0) g_nflag = 0;
}

// ---------------------------------------------------------------------------
// Kernel 0: transpose + 2-way bf16 split W[D,E] -> g_w_{h,m}[E][D]
// ---------------------------------------------------------------------------
__global__ __launch_bounds__(256)
void prep_w_kernel(const float* __restrict__ W)
{
    __shared__ float tile[32][33];
    const int eb = blockIdx.x * 32;
    const int kb = blockIdx.y * 32;
    const int x = threadIdx.x, y = threadIdx.y;
#pragma unroll
    for (int j = 0; j < 32; j += 8)
        tile[y + j][x] = W[(size_t)(kb + y + j) * E_EXP + eb + x];
    __syncthreads();
#pragma unroll
    for (int j = 0; j < 32; j += 8) {
        float w = tile[x][y + j];
        float h, m;
        split2(w, h, m);
        size_t o = (size_t)(eb + y + j) * D_DIM + kb + x;
        g_w_h[o] = __float2bfloat16(h);
        g_w_m[o] = __float2bfloat16(m);
    }
}

// ---------------------------------------------------------------------------
// GEMM stage helpers (validated R6/R9/R10 layout)
// ---------------------------------------------------------------------------
__device__ __forceinline__ void issue_w_cpasync(uint32_t stage_u32, int n_base, int k0, int tid)
{
#pragma unroll
    for (int j = 0; j < 4; j++) {
        int c = tid + j * 256;
        int row = c >> 3, seg = c & 7;
        size_t g = (size_t)(n_base + row) * D_DIM + k0 + seg * 8;
        uint32_t so = (uint32_t)(row * STRD + seg * 8) * 2;
        CP_ASYNC16(stage_u32 + OFF_WH + so, (const void*)(g_w_h + g));
        CP_ASYNC16(stage_u32 + OFF_WM + so, (const void*)(g_w_m + g));
    }
    CP_COMMIT();
}

__device__ __forceinline__ void issue_x_loads(const float* __restrict__ X,
                                              int m_base, int k0, int tid, float4 xa[8])
{
#pragma unroll
    for (int j = 0; j < 8; j++) {
        int f = tid + j * 256;
        int row = f >> 4, c4 = (f & 15) << 2;
        xa[j] = *(const float4*)(X + (size_t)(m_base + row) * D_DIM + k0 + c4);
    }
}

__device__ __forceinline__ void store_x(char* stage, int tid, const float4 xa[8])
{
#pragma unroll
    for (int j = 0; j < 8; j++) {
        int f = tid + j * 256;
        int row = f >> 4, c4 = (f & 15) << 2;
        float xs[4] = {xa[j].x, xa[j].y, xa[j].z, xa[j].w};
        float h[4], m[4];
#pragma unroll
        for (int e = 0; e < 4; e++) split2(xs[e], h[e], m[e]);
        uint32_t so = (uint32_t)(row * STRD + c4) * 2;
        *(uint2*)(stage + OFF_XH + so) = make_uint2(pack_bf2(h[0], h[1]), pack_bf2(h[2], h[3]));
        *(uint2*)(stage + OFF_XM + so) = make_uint2(pack_bf2(m[0], m[1]), pack_bf2(m[2], m[3]));
    }
}

__device__ __forceinline__ void compute_stage(const char* stage, int wm, int wn,
                                              int g, int q, float acc[4][4][4])
{
#pragma unroll
    for (int kk = 0; kk < 4; kk++) {
        uint32_t wh[4][2], wv[4][2];
#pragma unroll
        for (int nt = 0; nt < 4; nt++) {
            uint32_t off = ((uint32_t)(wn * 32 + nt * 8 + g) * STRD + kk * 16 + q * 2) * 2;
            wh[nt][0] = *(const uint32_t*)(stage + OFF_WH + off);
            wh[nt][1] = *(const uint32_t*)(stage + OFF_WH + off + 16);
            wv[nt][0] = *(const uint32_t*)(stage + OFF_WM + off);
            wv[nt][1] = *(const uint32_t*)(stage + OFF_WM + off + 16);
        }
#pragma unroll
        for (int mt = 0; mt < 4; mt++) {
            uint32_t off = ((uint32_t)(wm * 64 + mt * 16 + g) * STRD + kk * 16 + q * 2) * 2;
            const uint32_t r8 = 8 * STRD * 2;
            uint32_t xh[4], xm[4];
            xh[0] = *(const uint32_t*)(stage + OFF_XH + off);
            xh[1] = *(const uint32_t*)(stage + OFF_XH + off + r8);
            xh[2] = *(const uint32_t*)(stage + OFF_XH + off + 16);
            xh[3] = *(const uint32_t*)(stage + OFF_XH + off + r8 + 16);
            xm[0] = *(const uint32_t*)(stage + OFF_XM + off);
            xm[1] = *(const uint32_t*)(stage + OFF_XM + off + r8);
            xm[2] = *(const uint32_t*)(stage + OFF_XM + off + 16);
            xm[3] = *(const uint32_t*)(stage + OFF_XM + off + r8 + 16);
#pragma unroll
            for (int nt = 0; nt < 4; nt++) {
                mma16816(acc[mt][nt], xh, wh[nt]);   // hH
                mma16816(acc[mt][nt], xh, wv[nt]);   // hM
                mma16816(acc[mt][nt], xm, wh[nt]);   // mH
            }
        }
    }
}

// ---------------------------------------------------------------------------
// Kernel 1: bf16 2-way-split warp-MMA GEMM, SINGLE accumulator (no spills)
// ---------------------------------------------------------------------------
__global__ __launch_bounds__(256, 1)
void gemm_mma_kernel(const float* __restrict__ X)
{
    extern __shared__ __align__(16) char sm[];
    const uint32_t sm_u32 = s2u(sm);
    const int tid  = threadIdx.x;
    const int lane = tid & 31;
    const int wid  = tid >> 5;
    const int wm = wid & 1;
    const int wn = wid >> 1;
    const int g = lane >> 2;
    const int q = lane & 3;
    const int n_base = blockIdx.x * BN;
    const int m_base = blockIdx.y * BM;

    float acc[4][4][4];
#pragma unroll
    for (int a = 0; a < 4; a++)
#pragma unroll
        for (int b = 0; b < 4; b++)
#pragma unroll
            for (int c = 0; c < 4; c++) acc[a][b][c] = 0.0f;

    float4 xa[8];

    issue_w_cpasync(sm_u32, n_base, 0, tid);
    issue_x_loads(X, m_base, 0, tid, xa);
    store_x(sm, tid, xa);
    CP_WAIT0();
    __syncthreads();

    for (int ic = 0; ic < NCHUNK; ic++) {
        char* cur = sm + (size_t)(ic & 1) * STAGE_BYTES;
        char* nxt = sm + (size_t)((ic & 1) ^ 1) * STAGE_BYTES;
        const uint32_t nxt_u32 = sm_u32 + (uint32_t)(((ic & 1) ^ 1) * STAGE_BYTES);
        const bool pf = (ic + 1 < NCHUNK);
        if (pf) {
            issue_w_cpasync(nxt_u32, n_base, (ic + 1) * KC, tid);
            issue_x_loads(X, m_base, (ic + 1) * KC, tid, xa);
        }
        compute_stage(cur, wm, wn, g, q, acc);
        if (pf) store_x(nxt, tid, xa);
        CP_WAIT0();
        __syncthreads();
    }

#pragma unroll
    for (int mt = 0; mt < 4; mt++) {
#pragma unroll
        for (int nt = 0; nt < 4; nt++) {
            int row = m_base + wm * 64 + mt * 16 + g;
            int col = n_base + wn * 32 + nt * 8 + q * 2;
            float s0 = 1.0f / (1.0f + expf(-acc[mt][nt][0]));
            float s1 = 1.0f / (1.0f + expf(-acc[mt][nt][1]));
            float s2 = 1.0f / (1.0f + expf(-acc[mt][nt][2]));
            float s3 = 1.0f / (1.0f + expf(-acc[mt][nt][3]));
            *(float2*)(g_scores + (size_t)row * E_EXP + col)       = make_float2(s0, s1);
            *(float2*)(g_scores + (size_t)(row + 8) * E_EXP + col) = make_float2(s2, s3);
        }
    }
}

// ---------------------------------------------------------------------------
// Shared routing body. mode 0: flag borderline tokens. mode 1: force-write.
// ---------------------------------------------------------------------------
__device__ __forceinline__ void route_one(int t, const float* __restrict__ bias,
                                          float* __restrict__ out, int write_indices,
                                          int mode)
{
    __shared__ float score_sh[E_EXP];
    __shared__ float s_sh[E_EXP];
    __shared__ float gscore[N_GROUPS];
    __shared__ int   gsel[N_GROUPS];
    __shared__ float gmargin_sh;

    const int tid  = threadIdx.x;
    const int lane = tid & 31;
    const int wid  = tid >> 5;

    const float sc = g_scores[(size_t)t * E_EXP + tid];
    const float s  = sc + bias[tid];
    score_sh[tid] = sc;

    float v1 = s; int i1 = lane;
#pragma unroll
    for (int o = 16; o; o >>= 1) {
        float ov = __shfl_xor_sync(0xffffffffu, v1, o);
        int   oi = __shfl_xor_sync(0xffffffffu, i1, o);
        if (ov > v1 || (ov == v1 && oi < i1)) { v1 = ov; i1 = oi; }
    }
    float v2 = (lane == i1) ? -FLT_MAX : s;
#pragma unroll
    for (int o = 16; o; o >>= 1) {
        float ov = __shfl_xor_sync(0xffffffffu, v2, o);
        if (ov > v2) v2 = ov;
    }
    if (lane == 0) gscore[wid] = v1 + v2;
    if (tid < N_GROUPS) gsel[tid] = 0;
    __syncthreads();

    if (tid == 0) {
        float gg[N_GROUPS];
#pragma unroll
        for (int i = 0; i < N_GROUPS; i++) gg[i] = gscore[i];
        float v4 = 0.0f;
#pragma unroll
        for (int r = 0; r < TOPK_GROUPS; r++) {
            int best = 0; float bv = gg[0];
#pragma unroll
            for (int i = 1; i < N_GROUPS; i++)
                if (gg[i] > bv) { bv = gg[i]; best = i; }
            gsel[best] = 1;
            gg[best] = -FLT_MAX;
            v4 = bv;
        }
        float g5 = -FLT_MAX;
#pragma unroll
        for (int i = 0; i < N_GROUPS; i++)
            if (gg[i] > g5) g5 = gg[i];
        gmargin_sh = v4 - g5;
    }
    __syncthreads();

    s_sh[tid] = gsel[wid] ? s : 0.0f;
    __syncthreads();

    if (wid == 0) {
        float vals[8]; int idxs[8];
#pragma unroll
        for (int r = 0; r < 8; r++) {
            idxs[r] = r * 32 + lane;
            vals[r] = s_sh[idxs[r]];
        }
        int top[TOP_K];
        float topv9 = 0.0f, topv8 = 0.0f;
#pragma unroll
        for (int r = 0; r < TOP_K + 1; r++) {
            float bv = vals[0]; int bi = idxs[0]; int bslot = 0;
#pragma unroll
            for (int qq = 1; qq < 8; qq++)
                if (vals[qq] > bv || (vals[qq] == bv && idxs[qq] < bi)) {
                    bv = vals[qq]; bi = idxs[qq]; bslot = qq;
                }
            float wv2 = bv; int wi = bi;
#pragma unroll
            for (int o = 16; o; o >>= 1) {
                float ov = __shfl_xor_sync(0xffffffffu, wv2, o);
                int   oi = __shfl_xor_sync(0xffffffffu, wi, o);
                if (ov > wv2 || (ov == wv2 && oi < wi)) { wv2 = ov; wi = oi; }
            }
            if (bi == wi) vals[bslot] = -FLT_MAX;
            if (r < TOP_K) { top[r] = wi; if (r == TOP_K - 1) topv8 = wv2; }
            else           topv9 = wv2;
        }

        float w = 0.0f; int myidx = 0;
        if (lane < TOP_K) { myidx = top[lane]; w = score_sh[myidx]; }
        float sum = w;
#pragma unroll
        for (int o = 16; o; o >>= 1) sum += __shfl_xor_sync(0xffffffffu, sum, o);
        float weight = w / (sum + 1e-20f) * 2.5f;

        if (lane < TOP_K) {
            out[(size_t)t * TOP_K + lane] = weight;
            if (write_indices)
                out[(size_t)T_TOK * TOP_K + (size_t)t * TOP_K + lane] = (float)myidx;
        }

        if (mode == 0 && lane == 0) {
            bool safe = (gmargin_sh > EPS_G) && ((topv8 - topv9) > EPS_E);
            if (!safe) {
                int pos = atomicAdd(&g_nflag, 1);
                g_flaglist[pos] = t;
            }
        }
    }
    __syncthreads();
}

// ---------------------------------------------------------------------------
__global__ __launch_bounds__(256)
void router_kernel(const float* __restrict__ bias, float* __restrict__ out,
                   int write_indices)
{
    route_one(blockIdx.x, bias, out, write_indices, 0);
}

// ---------------------------------------------------------------------------
// Kernel 3: exact rescore of flagged tokens (bit-identical to R2 fp32 path)
// ---------------------------------------------------------------------------
#define RS_CHK 1024
__global__ __launch_bounds__(256)
void rescore_kernel(const float* __restrict__ X, const float* __restrict__ W)
{
    __shared__ float xs[2][RS_CHK];
    const int n = g_nflag;
    const int e = threadIdx.x;

    for (int base = blockIdx.x * 2; base < n; base += gridDim.x * 2) {
        const int t0 = g_flaglist[base];
        const bool has1 = (base + 1 < n);
        const int t1 = has1 ? g_flaglist[base + 1] : t0;

        float acc0 = 0.0f, acc1 = 0.0f;
        for (int k0 = 0; k0 < D_DIM; k0 += RS_CHK) {
            for (int idx = e; idx < 2 * RS_CHK; idx += 256) {
                int row = idx >> 10, k = idx & (RS_CHK - 1);
                int tt = row ? t1 : t0;
                xs[row][k] = X[(size_t)tt * D_DIM + k0 + k];
            }
            __syncthreads();
#pragma unroll 8
            for (int k = 0; k < RS_CHK; k++) {
                float w = W[(size_t)(k0 + k) * E_EXP + e];
                acc0 = fmaf(xs[0][k], w, acc0);
                acc1 = fmaf(xs[1][k], w, acc1);
            }
            __syncthreads();
        }
        g_scores[(size_t)t0 * E_EXP + e] = 1.0f / (1.0f + expf(-acc0));
        if (has1)
            g_scores[(size_t)t1 * E_EXP + e] = 1.0f / (1.0f + expf(-acc1));
    }
}

// ---------------------------------------------------------------------------
__global__ __launch_bounds__(256)
void router_fix_kernel(const float* __restrict__ bias, float* __restrict__ out,
                       int write_indices)
{
    const int n = g_nflag;
    for (int i = blockIdx.x; i < n; i += gridDim.x)
        route_one(g_flaglist[i], bias, out, write_indices, 1);
}

// ---------------------------------------------------------------------------
extern "C" void kernel_launch(void* const* d_in, const int* in_sizes, int n_in,
                              void* d_out, int out_size)
{
    const float* X    = (const float*)d_in[0];   // [T, D]
    const float* W    = (const float*)d_in[1];   // [D, E]
    const float* bias = (const float*)d_in[2];   // [E]
    float* out = (float*)d_out;

    cudaFuncSetAttribute(gemm_mma_kernel,
                         cudaFuncAttributeMaxDynamicSharedMemorySize, SMEM_BYTES);

    int write_indices = (out_size >= 2 * T_TOK * TOP_K) ? 1 : 0;

    zero_flags_kernel<<<1, 32>>>();
    prep_w_kernel<<<dim3(E_EXP / 32, D_DIM / 32), dim3(32, 8)>>>(W);
    gemm_mma_kernel<<<dim3(E_EXP / BN, T_TOK / BM), 256, SMEM_BYTES>>>(X);
    router_kernel<<<T_TOK, 256>>>(bias, out, write_indices);
    rescore_kernel<<<128, 256>>>(X, W);
    router_fix_kernel<<<256, 256>>>(bias, out, write_indices);
}